// round 16
// baseline (speedup 1.0000x reference)
#include <cuda_runtime.h>
#include <cuda_fp16.h>
#include <cstdint>
#include <cstddef>

// Problem constants
#define MTOT 16384      // B*S = 4*4096
#define HDIM 2048       // H
#define CHID 512        // CH
#define KIN  6144       // 3*H

// Layout inside g_hidden (in halfs):
//   [0, 8388608)          hidden fp16 (16384 x 512)
//   [8388608, 11534336)   W1h fp16 (512 x 6144)
//   [11534336, 12582912)  W2h fp16 (2048 x 512)
#define W1_OFF 8388608u
#define W2_OFF 11534336u

// Scratch: same proven global set. No new globals.
__device__ float2 g_stats[3 * MTOT];
__device__ float  g_hidden[(size_t)MTOT * CHID];

// GEMM tiling: BM=128, BN=128, BK=64, 256 threads (8 warps: 4M x 2N), 2 CTAs/SM
#define A_ST  16384                   // 128 rows * 128 B
#define STAGE (2 * A_ST)              // A + B per stage = 32768
#define SMEMB (2 * STAGE)             // 65536 dynamic; x2 CTAs = 128KB <= 228KB

__device__ __forceinline__ float gelu_exact(float x) {
    return 0.5f * x * (1.0f + erff(x * 0.70710678118654752440f));
}
__device__ __forceinline__ uint32_t smem_u32(const void* p) {
    uint32_t a;
    asm("{ .reg .u64 t; cvta.to.shared.u64 t, %1; cvt.u32.u64 %0, t; }" : "=r"(a) : "l"(p));
    return a;
}

// ---------------------------------------------------------------------------
// Kernel 1: per-row LayerNorm statistics (EXACT copy of the passing kernel)
// ---------------------------------------------------------------------------
__global__ void __launch_bounds__(256) ln_stats_kernel(
    const float* __restrict__ xp,
    const float* __restrict__ xu,
    const float* __restrict__ xz)
{
    const int m = blockIdx.x;
    const int t = blockIdx.y;
    const float* X = (t == 0) ? xp : ((t == 1) ? xu : xz);
    const float4* row = (const float4*)(X + (size_t)m * HDIM);

    float s = 0.f, sq = 0.f;
#pragma unroll
    for (int j = 0; j < 2; j++) {
        float4 v = row[threadIdx.x + j * 256];
        s  += v.x + v.y + v.z + v.w;
        sq += v.x * v.x + v.y * v.y + v.z * v.z + v.w * v.w;
    }

    __shared__ float s1[256], s2[256];
    s1[threadIdx.x] = s;
    s2[threadIdx.x] = sq;
    __syncthreads();
#pragma unroll
    for (int o = 128; o > 0; o >>= 1) {
        if (threadIdx.x < o) {
            s1[threadIdx.x] += s1[threadIdx.x + o];
            s2[threadIdx.x] += s2[threadIdx.x + o];
        }
        __syncthreads();
    }
    if (threadIdx.x == 0) {
        float mu  = s1[0] * (1.0f / HDIM);
        float var = s2[0] * (1.0f / HDIM) - mu * mu;
        g_stats[t * MTOT + m] = make_float2(mu, rsqrtf(var + 1e-5f));
    }
}

// ---------------------------------------------------------------------------
// Kernel 2: convert W1/W2 to fp16 into the spare upper half of g_hidden.
// ---------------------------------------------------------------------------
__global__ void __launch_bounds__(256) round_w_kernel(
    const float* __restrict__ W1, const float* __restrict__ W2)
{
    __half* Hbase = (__half*)g_hidden;
    const size_t n1 = (size_t)CHID * KIN / 4;
    const size_t n2 = (size_t)HDIM * CHID / 4;
    for (size_t i = (size_t)blockIdx.x * 256 + threadIdx.x; i < n1 + n2;
         i += (size_t)gridDim.x * 256) {
        float4 v = (i < n1) ? ((const float4*)W1)[i] : ((const float4*)W2)[i - n1];
        __half2 h0 = __floats2half2_rn(v.x, v.y);
        __half2 h1 = __floats2half2_rn(v.z, v.w);
        uint2 o = make_uint2(*(uint32_t*)&h0, *(uint32_t*)&h1);
        if (i < n1) ((uint2*)(Hbase + W1_OFF))[i]      = o;
        else        ((uint2*)(Hbase + W2_OFF))[i - n1] = o;
    }
}

// ---------------------------------------------------------------------------
// fp16 mma GEMM: 256 threads, reg-capped for 2 CTAs/SM. R13 fragment path.
// LN transform applied at LDG time; prefetched A kept as packed fp16.
// ---------------------------------------------------------------------------
template<bool LN_A, bool GELU, int N, int K>
__global__ void __launch_bounds__(256, 2) gemm_fp16_kernel(
    const float* __restrict__ x0, const float* __restrict__ x1, const float* __restrict__ x2,
    const float* __restrict__ g0, const float* __restrict__ g1, const float* __restrict__ g2,
    const float* __restrict__ c0, const float* __restrict__ c1, const float* __restrict__ c2,
    unsigned int woff,                // W offset in halfs within g_hidden
    const float* __restrict__ bias,   // [N]
    float* __restrict__ Cout)         // [M][N] fp32
{
    extern __shared__ __align__(16) unsigned char smem[];

    const int bm   = blockIdx.y * 128;
    const int bn   = blockIdx.x * 128;
    const int tid  = threadIdx.x;
    const int lane = tid & 31;
    const int warp = tid >> 5;
    const int warpM = warp & 3;       // 0..3 -> 32-row slices
    const int warpN = warp >> 2;      // 0..1 -> 64-col slices
    const int g = lane >> 2;
    const int t = lane & 3;

    // staging geometry: rows x 8 chunks(16B); 256 thr -> rbase 0..31, 4 rows each
    const int rbase = tid >> 3;
    const int cchnk = tid & 7;

    const uint32_t sb = smem_u32(smem);

    // ldmatrix lane addressing (identical formulas to R13)
    const int rowA = warpM * 32 + (lane & 15);
    const int aSel = lane >> 4;
    const int q    = lane >> 3;
    const int rowB = warpN * 64 + ((q >> 1) << 3) + (lane & 7);
    const int bSel = q & 1;
    const int sw7  = lane & 7;

    float acc[2][8][4];
#pragma unroll
    for (int i = 0; i < 2; i++)
#pragma unroll
        for (int j = 0; j < 8; j++)
#pragma unroll
            for (int r = 0; r < 4; r++) acc[i][j][r] = 0.f;

    const __half* Wh = (const __half*)g_hidden + woff;
    const __half* Ah = (const __half*)g_hidden;

    // prefetch registers: packed fp16 only (reg diet for 2 CTAs/SM)
    uint4 rAh[4];                     // A rows rbase + j*32, LN applied, fp16
    uint4 rWq[4];                     // B rows rbase + j*32, fp16

    auto ldg_tile = [&](int k0) {
        const int kb = k0 + cchnk * 8;
        if (LN_A) {
            const int tt = kb >> 11;
            const int kk = kb & 2047;
            const float* X  = (tt == 0) ? x0 : ((tt == 1) ? x1 : x2);
            const float* G  = (tt == 0) ? g0 : ((tt == 1) ? g1 : g2);
            const float* Bb = (tt == 0) ? c0 : ((tt == 1) ? c1 : c2);
            const float4 ga = *(const float4*)(G + kk);
            const float4 gb = *(const float4*)(G + kk + 4);
            const float4 ba = *(const float4*)(Bb + kk);
            const float4 bb = *(const float4*)(Bb + kk + 4);
#pragma unroll
            for (int j = 0; j < 4; j++) {
                const int m = bm + rbase + j * 32;
                const float2 st = g_stats[tt * MTOT + m];
                float4 va = *(const float4*)(X + (size_t)m * HDIM + kk);
                float4 vb = *(const float4*)(X + (size_t)m * HDIM + kk + 4);
                const float mu = st.x, rs = st.y;
                va.x = (va.x - mu) * rs * ga.x + ba.x;
                va.y = (va.y - mu) * rs * ga.y + ba.y;
                va.z = (va.z - mu) * rs * ga.z + ba.z;
                va.w = (va.w - mu) * rs * ga.w + ba.w;
                vb.x = (vb.x - mu) * rs * gb.x + bb.x;
                vb.y = (vb.y - mu) * rs * gb.y + bb.y;
                vb.z = (vb.z - mu) * rs * gb.z + bb.z;
                vb.w = (vb.w - mu) * rs * gb.w + bb.w;
                __half2 h0 = __floats2half2_rn(va.x, va.y);
                __half2 h1 = __floats2half2_rn(va.z, va.w);
                __half2 h2 = __floats2half2_rn(vb.x, vb.y);
                __half2 h3 = __floats2half2_rn(vb.z, vb.w);
                rAh[j] = make_uint4(*(uint32_t*)&h0, *(uint32_t*)&h1,
                                    *(uint32_t*)&h2, *(uint32_t*)&h3);
            }
        } else {
#pragma unroll
            for (int j = 0; j < 4; j++) {
                const int m = bm + rbase + j * 32;
                rAh[j] = *(const uint4*)(Ah + (size_t)m * K + kb);
            }
        }
#pragma unroll
        for (int j = 0; j < 4; j++) {
            const int n = bn + rbase + j * 32;
            rWq[j] = *(const uint4*)(Wh + (size_t)n * K + kb);
        }
    };

    auto sts_tile = [&](int buf) {
        const uint32_t As = (uint32_t)(buf * STAGE);
        const uint32_t Bs = As + A_ST;
#pragma unroll
        for (int j = 0; j < 4; j++) {
            const int r = rbase + j * 32;
            const uint32_t off = (uint32_t)(r * 128 + ((cchnk ^ (r & 7)) << 4));
            *(uint4*)(smem + As + off) = rAh[j];
            *(uint4*)(smem + Bs + off) = rWq[j];
        }
    };

    constexpr int NT = K / 64;

    ldg_tile(0);
    sts_tile(0);
    __syncthreads();
    if (NT > 1) ldg_tile(64);

    for (int i = 0; i < NT; i++) {
        if (i + 1 < NT) sts_tile((i + 1) & 1);
        if (i + 2 < NT) ldg_tile((i + 2) * 64);

        const uint32_t stg = (uint32_t)((i & 1) * STAGE);
#pragma unroll
        for (int kk = 0; kk < 4; kk++) {
            uint32_t a[2][4], b[8][2];
            const uint32_t aswz = (uint32_t)((((kk * 2 + aSel) ^ sw7) & 7) << 4);
            const uint32_t bswz = (uint32_t)((((kk * 2 + bSel) ^ sw7) & 7) << 4);
#pragma unroll
            for (int mt = 0; mt < 2; mt++) {
                asm volatile(
                    "ldmatrix.sync.aligned.m8n8.x4.shared.b16 {%0,%1,%2,%3}, [%4];"
                    : "=r"(a[mt][0]), "=r"(a[mt][1]), "=r"(a[mt][2]), "=r"(a[mt][3])
                    : "r"(sb + stg + (uint32_t)((rowA + mt * 16) * 128) + aswz));
            }
#pragma unroll
            for (int np = 0; np < 4; np++) {
                asm volatile(
                    "ldmatrix.sync.aligned.m8n8.x4.shared.b16 {%0,%1,%2,%3}, [%4];"
                    : "=r"(b[np * 2][0]), "=r"(b[np * 2][1]),
                      "=r"(b[np * 2 + 1][0]), "=r"(b[np * 2 + 1][1])
                    : "r"(sb + stg + A_ST + (uint32_t)((rowB + np * 16) * 128) + bswz));
            }
#pragma unroll
            for (int mt = 0; mt < 2; mt++)
#pragma unroll
                for (int nt = 0; nt < 8; nt++)
                    asm volatile(
                        "mma.sync.aligned.m16n8k16.row.col.f32.f16.f16.f32 "
                        "{%0,%1,%2,%3}, {%4,%5,%6,%7}, {%8,%9}, {%0,%1,%2,%3};\n"
                        : "+f"(acc[mt][nt][0]), "+f"(acc[mt][nt][1]),
                          "+f"(acc[mt][nt][2]), "+f"(acc[mt][nt][3])
                        : "r"(a[mt][0]), "r"(a[mt][1]), "r"(a[mt][2]), "r"(a[mt][3]),
                          "r"(b[nt][0]), "r"(b[nt][1]));
        }
        __syncthreads();
    }

    // ---- epilogue (identical to R13) ----
#pragma unroll
    for (int mt = 0; mt < 2; mt++) {
        int row = bm + warpM * 32 + mt * 16 + g;
#pragma unroll
        for (int nt = 0; nt < 8; nt++) {
            int col = bn + warpN * 64 + nt * 8 + (t << 1);
            float bs0 = bias[col], bs1 = bias[col + 1];
            float v0 = acc[mt][nt][0] + bs0;
            float v1 = acc[mt][nt][1] + bs1;
            float v2 = acc[mt][nt][2] + bs0;
            float v3 = acc[mt][nt][3] + bs1;
            if (GELU) {
                __half* Hd = (__half*)g_hidden;
                __half2 h0 = __floats2half2_rn(gelu_exact(v0), gelu_exact(v1));
                __half2 h1 = __floats2half2_rn(gelu_exact(v2), gelu_exact(v3));
                *(uint32_t*)(Hd + (size_t)row * N + col)       = *(uint32_t*)&h0;
                *(uint32_t*)(Hd + (size_t)(row + 8) * N + col) = *(uint32_t*)&h1;
            } else {
                Cout[(size_t)row * N + col]           = v0;
                Cout[(size_t)row * N + col + 1]       = v1;
                Cout[(size_t)(row + 8) * N + col]     = v2;
                Cout[(size_t)(row + 8) * N + col + 1] = v3;
            }
        }
    }
}

// ---------------------------------------------------------------------------
extern "C" void kernel_launch(void* const* d_in, const int* in_sizes, int n_in,
                              void* d_out, int out_size)
{
    const float* u_t    = (const float*)d_in[0];
    const float* z_t    = (const float*)d_in[1];
    const float* prev   = (const float*)d_in[2];
    const float* prev_g = (const float*)d_in[3];
    const float* prev_b = (const float*)d_in[4];
    const float* u_g    = (const float*)d_in[5];
    const float* u_b    = (const float*)d_in[6];
    const float* z_g    = (const float*)d_in[7];
    const float* z_b    = (const float*)d_in[8];
    const float* W1     = (const float*)d_in[9];
    const float* b1     = (const float*)d_in[10];
    const float* W2     = (const float*)d_in[11];
    const float* b2     = (const float*)d_in[12];
    float* out = (float*)d_out;

    cudaFuncSetAttribute(gemm_fp16_kernel<true,  true,  CHID, KIN>,
                         cudaFuncAttributeMaxDynamicSharedMemorySize, SMEMB);
    cudaFuncSetAttribute(gemm_fp16_kernel<false, false, HDIM, CHID>,
                         cudaFuncAttributeMaxDynamicSharedMemorySize, SMEMB);
    cudaFuncSetAttribute(gemm_fp16_kernel<true,  true,  CHID, KIN>,
                         cudaFuncAttributePreferredSharedMemoryCarveout, 100);
    cudaFuncSetAttribute(gemm_fp16_kernel<false, false, HDIM, CHID>,
                         cudaFuncAttributePreferredSharedMemoryCarveout, 100);

    // 1) LN statistics
    ln_stats_kernel<<<dim3(MTOT, 3), 256>>>(prev, u_t, z_t);

    // 2) W1/W2 -> fp16 (into spare region of g_hidden)
    round_w_kernel<<<2048, 256>>>(W1, W2);

    // 3) GEMM1: hidden(fp16) = gelu(LN-concat @ W1h^T + b1)   [16384 x 512]
    gemm_fp16_kernel<true, true, CHID, KIN>
        <<<dim3(CHID / 128, MTOT / 128), 256, SMEMB>>>(
        prev, u_t, z_t,
        prev_g, u_g, z_g,
        prev_b, u_b, z_b,
        W1_OFF, b1, nullptr);

    // 4) GEMM2: out = hidden @ W2h^T + b2                     [16384 x 2048]
    gemm_fp16_kernel<false, false, HDIM, CHID>
        <<<dim3(HDIM / 128, MTOT / 128), 256, SMEMB>>>(
        nullptr, nullptr, nullptr,
        nullptr, nullptr, nullptr,
        nullptr, nullptr, nullptr,
        W2_OFF, b2, out);
}

// round 17
// speedup vs baseline: 1.0922x; 1.0922x over previous
#include <cuda_runtime.h>
#include <cuda_fp16.h>
#include <cstdint>
#include <cstddef>

// Problem constants
#define MTOT 16384      // B*S = 4*4096
#define HDIM 2048       // H
#define CHID 512        // CH
#define KIN  6144       // 3*H

// Layout inside g_hidden (in halfs):
//   [0, 8388608)          hidden fp16 (16384 x 512)
//   [8388608, 11534336)   W1h fp16 (512 x 6144)
//   [11534336, 12582912)  W2h fp16 (2048 x 512)
#define W1_OFF 8388608u
#define W2_OFF 11534336u

// Scratch: same proven global set. No new globals.
__device__ float2 g_stats[3 * MTOT];
__device__ float  g_hidden[(size_t)MTOT * CHID];

// GEMM tiling: BM=256, BN=128, BK=64, 256 threads (8 warps: 4M x 2N),
// warp tile 64x64 (mt=4, nt=8). 2-stage ping-pong, 96KB dynamic smem.
#define A_ST  32768                   // 256 rows * 128 B
#define B_ST  16384                   // 128 rows * 128 B
#define STAGE (A_ST + B_ST)           // 49152
#define SMEMB (2 * STAGE)             // 98304

__device__ __forceinline__ float gelu_exact(float x) {
    return 0.5f * x * (1.0f + erff(x * 0.70710678118654752440f));
}
__device__ __forceinline__ uint32_t smem_u32(const void* p) {
    uint32_t a;
    asm("{ .reg .u64 t; cvta.to.shared.u64 t, %1; cvt.u32.u64 %0, t; }" : "=r"(a) : "l"(p));
    return a;
}
__device__ __forceinline__ void cp16(uint32_t dst, const void* src) {
    asm volatile("cp.async.cg.shared.global [%0], [%1], 16;" :: "r"(dst), "l"(src) : "memory");
}

// ---------------------------------------------------------------------------
// Kernel 1: per-row LayerNorm statistics (EXACT copy of the passing kernel)
// ---------------------------------------------------------------------------
__global__ void __launch_bounds__(256) ln_stats_kernel(
    const float* __restrict__ xp,
    const float* __restrict__ xu,
    const float* __restrict__ xz)
{
    const int m = blockIdx.x;
    const int t = blockIdx.y;
    const float* X = (t == 0) ? xp : ((t == 1) ? xu : xz);
    const float4* row = (const float4*)(X + (size_t)m * HDIM);

    float s = 0.f, sq = 0.f;
#pragma unroll
    for (int j = 0; j < 2; j++) {
        float4 v = row[threadIdx.x + j * 256];
        s  += v.x + v.y + v.z + v.w;
        sq += v.x * v.x + v.y * v.y + v.z * v.z + v.w * v.w;
    }

    __shared__ float s1[256], s2[256];
    s1[threadIdx.x] = s;
    s2[threadIdx.x] = sq;
    __syncthreads();
#pragma unroll
    for (int o = 128; o > 0; o >>= 1) {
        if (threadIdx.x < o) {
            s1[threadIdx.x] += s1[threadIdx.x + o];
            s2[threadIdx.x] += s2[threadIdx.x + o];
        }
        __syncthreads();
    }
    if (threadIdx.x == 0) {
        float mu  = s1[0] * (1.0f / HDIM);
        float var = s2[0] * (1.0f / HDIM) - mu * mu;
        g_stats[t * MTOT + m] = make_float2(mu, rsqrtf(var + 1e-5f));
    }
}

// ---------------------------------------------------------------------------
// Kernel 2: convert W1/W2 to fp16 into the spare upper half of g_hidden.
// ---------------------------------------------------------------------------
__global__ void __launch_bounds__(256) round_w_kernel(
    const float* __restrict__ W1, const float* __restrict__ W2)
{
    __half* Hbase = (__half*)g_hidden;
    const size_t n1 = (size_t)CHID * KIN / 4;
    const size_t n2 = (size_t)HDIM * CHID / 4;
    for (size_t i = (size_t)blockIdx.x * 256 + threadIdx.x; i < n1 + n2;
         i += (size_t)gridDim.x * 256) {
        float4 v = (i < n1) ? ((const float4*)W1)[i] : ((const float4*)W2)[i - n1];
        __half2 h0 = __floats2half2_rn(v.x, v.y);
        __half2 h1 = __floats2half2_rn(v.z, v.w);
        uint2 o = make_uint2(*(uint32_t*)&h0, *(uint32_t*)&h1);
        if (i < n1) ((uint2*)(Hbase + W1_OFF))[i]      = o;
        else        ((uint2*)(Hbase + W2_OFF))[i - n1] = o;
    }
}

// ---------------------------------------------------------------------------
// fp16 mma GEMM: BM=256, warp tile 64x64 (128 B/mma ldmatrix traffic).
// B (and A when fp16-sourced) staged by cp.async; GEMM1 LN-A staged through
// registers (LDG -> LN -> fp16 pack -> STS).
// ---------------------------------------------------------------------------
template<bool LN_A, bool GELU, int N, int K>
__global__ void __launch_bounds__(256) gemm_fp16_kernel(
    const float* __restrict__ x0, const float* __restrict__ x1, const float* __restrict__ x2,
    const float* __restrict__ g0, const float* __restrict__ g1, const float* __restrict__ g2,
    const float* __restrict__ c0, const float* __restrict__ c1, const float* __restrict__ c2,
    unsigned int woff,                // W offset in halfs within g_hidden
    const float* __restrict__ bias,   // [N]
    float* __restrict__ Cout)         // [M][N] fp32
{
    extern __shared__ __align__(16) unsigned char smem[];

    const int bm   = blockIdx.y * 256;
    const int bn   = blockIdx.x * 128;
    const int tid  = threadIdx.x;
    const int lane = tid & 31;
    const int warp = tid >> 5;
    const int warpM = warp & 3;       // 0..3 -> 64-row slices
    const int warpN = warp >> 2;      // 0..1 -> 64-col slices
    const int g = lane >> 2;
    const int t = lane & 3;

    // staging geometry: rows x 8 chunks(16B); rbase 0..31
    const int rbase = tid >> 3;
    const int cchnk = tid & 7;

    const uint32_t sb = smem_u32(smem);

    // ldmatrix lane addressing
    const int rowA = warpM * 64 + (lane & 15);            // + mt*16
    const int aSel = lane >> 4;
    const int q    = lane >> 3;
    const int rowB = warpN * 64 + ((q >> 1) << 3) + (lane & 7);  // + np*16
    const int bSel = q & 1;
    const int sw7  = lane & 7;

    float acc[4][8][4];
#pragma unroll
    for (int i = 0; i < 4; i++)
#pragma unroll
        for (int j = 0; j < 8; j++)
#pragma unroll
            for (int r = 0; r < 4; r++) acc[i][j][r] = 0.f;

    const __half* Wh = (const __half*)g_hidden + woff;
    const __half* Ah = (const __half*)g_hidden;

    // LN-A prefetch registers: 8 rows of packed fp16 (GEMM1 only)
    uint4 rAh[8];

    // ---- LN-A: global -> registers (LN + fp16 pack) ----
    auto ldg_tileA = [&](int k0) {
        if (!LN_A) return;
        const int kb = k0 + cchnk * 8;
        const int tt = kb >> 11;
        const int kk = kb & 2047;
        const float* X  = (tt == 0) ? x0 : ((tt == 1) ? x1 : x2);
        const float* G  = (tt == 0) ? g0 : ((tt == 1) ? g1 : g2);
        const float* Bb = (tt == 0) ? c0 : ((tt == 1) ? c1 : c2);
        const float4 ga = *(const float4*)(G + kk);
        const float4 gb = *(const float4*)(G + kk + 4);
        const float4 ba = *(const float4*)(Bb + kk);
        const float4 bb = *(const float4*)(Bb + kk + 4);
#pragma unroll
        for (int j = 0; j < 8; j++) {
            const int m = bm + rbase + j * 32;
            const float2 st = g_stats[tt * MTOT + m];
            float4 va = *(const float4*)(X + (size_t)m * HDIM + kk);
            float4 vb = *(const float4*)(X + (size_t)m * HDIM + kk + 4);
            const float mu = st.x, rs = st.y;
            va.x = (va.x - mu) * rs * ga.x + ba.x;
            va.y = (va.y - mu) * rs * ga.y + ba.y;
            va.z = (va.z - mu) * rs * ga.z + ba.z;
            va.w = (va.w - mu) * rs * ga.w + ba.w;
            vb.x = (vb.x - mu) * rs * gb.x + bb.x;
            vb.y = (vb.y - mu) * rs * gb.y + bb.y;
            vb.z = (vb.z - mu) * rs * gb.z + bb.z;
            vb.w = (vb.w - mu) * rs * gb.w + bb.w;
            __half2 h0 = __floats2half2_rn(va.x, va.y);
            __half2 h1 = __floats2half2_rn(va.z, va.w);
            __half2 h2 = __floats2half2_rn(vb.x, vb.y);
            __half2 h3 = __floats2half2_rn(vb.z, vb.w);
            rAh[j] = make_uint4(*(uint32_t*)&h0, *(uint32_t*)&h1,
                                *(uint32_t*)&h2, *(uint32_t*)&h3);
        }
    };

    // ---- LN-A: registers -> shared ----
    auto sts_tileA = [&](int buf) {
        if (!LN_A) return;
        const uint32_t As = (uint32_t)(buf * STAGE);
#pragma unroll
        for (int j = 0; j < 8; j++) {
            const int r = rbase + j * 32;
            const uint32_t off = (uint32_t)(r * 128 + ((cchnk ^ (r & 7)) << 4));
            *(uint4*)(smem + As + off) = rAh[j];
        }
    };

    // ---- pure-copy staging via cp.async (B always; A when fp16 source) ----
    auto cp_tile = [&](int k0, int buf) {
        const int kb = k0 + cchnk * 8;
        const uint32_t As = sb + (uint32_t)(buf * STAGE);
        const uint32_t Bs = As + A_ST;
#pragma unroll
        for (int j = 0; j < 4; j++) {
            const int r = rbase + j * 32;
            const uint32_t off = (uint32_t)(r * 128 + ((cchnk ^ (r & 7)) << 4));
            cp16(Bs + off, Wh + (size_t)(bn + r) * K + kb);
        }
        if (!LN_A) {
#pragma unroll
            for (int j = 0; j < 8; j++) {
                const int r = rbase + j * 32;
                const uint32_t off = (uint32_t)(r * 128 + ((cchnk ^ (r & 7)) << 4));
                cp16(As + off, Ah + (size_t)(bm + r) * K + kb);
            }
        }
        asm volatile("cp.async.commit_group;" ::: "memory");
    };

    constexpr int NT = K / 64;

    // ---- prologue: stage tile 0, prefetch LN tile 1 ----
    ldg_tileA(0);
    cp_tile(0, 0);
    sts_tileA(0);
    if (NT > 1) ldg_tileA(64);
    asm volatile("cp.async.wait_group 0;" ::: "memory");
    __syncthreads();

    for (int i = 0; i < NT; i++) {
        if (i + 1 < NT) {
            cp_tile((i + 1) * 64, (i + 1) & 1);
            sts_tileA((i + 1) & 1);               // rAh holds tile i+1
            if (i + 2 < NT) ldg_tileA((i + 2) * 64);
        }

        const uint32_t stg = (uint32_t)((i & 1) * STAGE);
#pragma unroll
        for (int kk = 0; kk < 4; kk++) {
            uint32_t a[4][4], b[8][2];
            const uint32_t aswz = (uint32_t)((((kk * 2 + aSel) ^ sw7) & 7) << 4);
            const uint32_t bswz = (uint32_t)((((kk * 2 + bSel) ^ sw7) & 7) << 4);
#pragma unroll
            for (int mt = 0; mt < 4; mt++) {
                asm volatile(
                    "ldmatrix.sync.aligned.m8n8.x4.shared.b16 {%0,%1,%2,%3}, [%4];"
                    : "=r"(a[mt][0]), "=r"(a[mt][1]), "=r"(a[mt][2]), "=r"(a[mt][3])
                    : "r"(sb + stg + (uint32_t)((rowA + mt * 16) * 128) + aswz));
            }
#pragma unroll
            for (int np = 0; np < 4; np++) {
                asm volatile(
                    "ldmatrix.sync.aligned.m8n8.x4.shared.b16 {%0,%1,%2,%3}, [%4];"
                    : "=r"(b[np * 2][0]), "=r"(b[np * 2][1]),
                      "=r"(b[np * 2 + 1][0]), "=r"(b[np * 2 + 1][1])
                    : "r"(sb + stg + A_ST + (uint32_t)((rowB + np * 16) * 128) + bswz));
            }
#pragma unroll
            for (int mt = 0; mt < 4; mt++)
#pragma unroll
                for (int nt = 0; nt < 8; nt++)
                    asm volatile(
                        "mma.sync.aligned.m16n8k16.row.col.f32.f16.f16.f32 "
                        "{%0,%1,%2,%3}, {%4,%5,%6,%7}, {%8,%9}, {%0,%1,%2,%3};\n"
                        : "+f"(acc[mt][nt][0]), "+f"(acc[mt][nt][1]),
                          "+f"(acc[mt][nt][2]), "+f"(acc[mt][nt][3])
                        : "r"(a[mt][0]), "r"(a[mt][1]), "r"(a[mt][2]), "r"(a[mt][3]),
                          "r"(b[nt][0]), "r"(b[nt][1]));
        }
        if (i + 1 < NT)
            asm volatile("cp.async.wait_group 0;" ::: "memory");
        __syncthreads();
    }

    // ---- epilogue (per-warp mapping as before, mt now 0..3 over 64 rows) ----
#pragma unroll
    for (int mt = 0; mt < 4; mt++) {
        int row = bm + warpM * 64 + mt * 16 + g;
#pragma unroll
        for (int nt = 0; nt < 8; nt++) {
            int col = bn + warpN * 64 + nt * 8 + (t << 1);
            float bs0 = bias[col], bs1 = bias[col + 1];
            float v0 = acc[mt][nt][0] + bs0;
            float v1 = acc[mt][nt][1] + bs1;
            float v2 = acc[mt][nt][2] + bs0;
            float v3 = acc[mt][nt][3] + bs1;
            if (GELU) {
                __half* Hd = (__half*)g_hidden;
                __half2 h0 = __floats2half2_rn(gelu_exact(v0), gelu_exact(v1));
                __half2 h1 = __floats2half2_rn(gelu_exact(v2), gelu_exact(v3));
                *(uint32_t*)(Hd + (size_t)row * N + col)       = *(uint32_t*)&h0;
                *(uint32_t*)(Hd + (size_t)(row + 8) * N + col) = *(uint32_t*)&h1;
            } else {
                Cout[(size_t)row * N + col]           = v0;
                Cout[(size_t)row * N + col + 1]       = v1;
                Cout[(size_t)(row + 8) * N + col]     = v2;
                Cout[(size_t)(row + 8) * N + col + 1] = v3;
            }
        }
    }
}

// ---------------------------------------------------------------------------
extern "C" void kernel_launch(void* const* d_in, const int* in_sizes, int n_in,
                              void* d_out, int out_size)
{
    const float* u_t    = (const float*)d_in[0];
    const float* z_t    = (const float*)d_in[1];
    const float* prev   = (const float*)d_in[2];
    const float* prev_g = (const float*)d_in[3];
    const float* prev_b = (const float*)d_in[4];
    const float* u_g    = (const float*)d_in[5];
    const float* u_b    = (const float*)d_in[6];
    const float* z_g    = (const float*)d_in[7];
    const float* z_b    = (const float*)d_in[8];
    const float* W1     = (const float*)d_in[9];
    const float* b1     = (const float*)d_in[10];
    const float* W2     = (const float*)d_in[11];
    const float* b2     = (const float*)d_in[12];
    float* out = (float*)d_out;

    cudaFuncSetAttribute(gemm_fp16_kernel<true,  true,  CHID, KIN>,
                         cudaFuncAttributeMaxDynamicSharedMemorySize, SMEMB);
    cudaFuncSetAttribute(gemm_fp16_kernel<false, false, HDIM, CHID>,
                         cudaFuncAttributeMaxDynamicSharedMemorySize, SMEMB);

    // 1) LN statistics
    ln_stats_kernel<<<dim3(MTOT, 3), 256>>>(prev, u_t, z_t);

    // 2) W1/W2 -> fp16 (into spare region of g_hidden)
    round_w_kernel<<<2048, 256>>>(W1, W2);

    // 3) GEMM1: hidden(fp16) = gelu(LN-concat @ W1h^T + b1)   [16384 x 512]
    gemm_fp16_kernel<true, true, CHID, KIN>
        <<<dim3(CHID / 128, MTOT / 256), 256, SMEMB>>>(
        prev, u_t, z_t,
        prev_g, u_g, z_g,
        prev_b, u_b, z_b,
        W1_OFF, b1, nullptr);

    // 4) GEMM2: out = hidden @ W2h^T + b2                     [16384 x 2048]
    gemm_fp16_kernel<false, false, HDIM, CHID>
        <<<dim3(HDIM / 128, MTOT / 256), 256, SMEMB>>>(
        nullptr, nullptr, nullptr,
        nullptr, nullptr, nullptr,
        nullptr, nullptr, nullptr,
        W2_OFF, b2, out);
}